// round 2
// baseline (speedup 1.0000x reference)
#include <cuda_runtime.h>
#include <math.h>

// ---------------------------------------------------------------------------
// Problem constants
// ---------------------------------------------------------------------------
#define BB     32
#define L_IN   336
#define MM     64
#define PP     16
#define STRIDE 4
#define NTOK   81                    // (336-16)/4 + 1
#define DM     512
#define NH     8
#define EH     64
#define DFF    1024
#define NL     3
#define RT     (2048 * 81)           // 165888 tokens total (B*M*N)
#define RTILES (RT / 128)            // 1296

// ---------------------------------------------------------------------------
// Scratch (device globals: no cudaMalloc allowed)
// ---------------------------------------------------------------------------
__device__ float g_h  [RT * DM];
__device__ float g_q  [RT * DM];
__device__ float g_k  [RT * DM];
__device__ float g_v  [RT * DM];
__device__ float g_att[RT * DM];
__device__ float g_y  [RT * DM];
__device__ float g_t  [RT * DFF];
__device__ float g_psum[512 * 512];
__device__ float g_psq [512 * 512];
__device__ float g_scale[512];
__device__ float g_shift[512];

// ---------------------------------------------------------------------------
// Token embedding: circular Conv1d(P->D,k=3) over patch axis + sinusoidal PE
// grid = 2048 (one block per bm), 256 threads, dynamic smem
// ---------------------------------------------------------------------------
#define EMB_SMEM_FLOATS (512 * 49 + 336)
__global__ void embed_kernel(const float* __restrict__ x_enc,
                             const float* __restrict__ tok_w,
                             float* __restrict__ h)
{
    extern __shared__ float sm[];
    float* w_sm = sm;               // [512][49] padded (49 coprime w/ 32 banks)
    float* x_sm = sm + 512 * 49;    // [336]
    int bm = blockIdx.x;
    int b = bm >> 6, m = bm & 63;
    int tid = threadIdx.x;

    for (int i = tid; i < 512 * 48; i += 256) {
        int d = i / 48, u = i - d * 48;
        w_sm[d * 49 + u] = tok_w[i];
    }
    for (int l = tid; l < 336; l += 256)
        x_sm[l] = x_enc[(b * 336 + l) * 64 + m];
    __syncthreads();

    const float CLOG = -9.210340371976184f / 256.0f;  // -ln(10000)/256
    int d0 = tid, d1 = tid + 256;
    float fr0 = expf((float)(d0 >> 1) * CLOG);
    float fr1 = expf((float)(d1 >> 1) * CLOG);

    for (int n = 0; n < NTOK; n++) {
        float a0 = 0.f, a1 = 0.f;
        #pragma unroll
        for (int t = 0; t < 3; t++) {
            int pp = n - 1 + t;
            pp = (pp < 0) ? (NTOK - 1) : (pp >= NTOK ? 0 : pp);
            const float* xp = x_sm + pp * 4;
            #pragma unroll
            for (int p = 0; p < 16; p++) {
                float xv = xp[p];
                a0 += xv * w_sm[d0 * 49 + p * 3 + t];
                a1 += xv * w_sm[d1 * 49 + p * 3 + t];
            }
        }
        float ang0 = (float)n * fr0, ang1 = (float)n * fr1;
        float pe0 = (d0 & 1) ? cosf(ang0) : sinf(ang0);
        float pe1 = (d1 & 1) ? cosf(ang1) : sinf(ang1);
        size_t base = ((size_t)bm * NTOK + n) * DM;
        h[base + d0] = a0 + pe0;
        h[base + d1] = a1 + pe1;
    }
}

// ---------------------------------------------------------------------------
// SGEMM: C[r,o] = sum_k A[r,k] * W[o,k]  (+bias, optional GELU / residual)
// 128x128 tile, BK=8, 256 threads, 8x8 per-thread microtile.
// grid = (Dout/128, RT/128). EPI: 0=bias, 1=bias+gelu, 2=bias+residual
// ---------------------------------------------------------------------------
template <int EPI>
__global__ __launch_bounds__(256)
void sgemm_kernel(const float* __restrict__ A, const float* __restrict__ W,
                  const float* __restrict__ bias, const float* __restrict__ res,
                  float* __restrict__ C, int K)
{
    __shared__ float As[8][128];
    __shared__ float Bs[8][128];
    int col0 = blockIdx.x * 128;
    int row0 = blockIdx.y * 128;
    int Dout = gridDim.x * 128;
    int tid = threadIdx.x;
    int tx = tid & 15, ty = tid >> 4;
    int lr = tid >> 1;
    int lk = (tid & 1) * 4;

    const float* Aptr = A + (size_t)(row0 + lr) * K + lk;
    const float* Wptr = W + (size_t)(col0 + lr) * K + lk;

    float acc[8][8];
    #pragma unroll
    for (int i = 0; i < 8; i++)
        #pragma unroll
        for (int j = 0; j < 8; j++) acc[i][j] = 0.f;

    for (int kt = 0; kt < K; kt += 8) {
        float4 a4 = *(const float4*)(Aptr + kt);
        float4 b4 = *(const float4*)(Wptr + kt);
        As[lk + 0][lr] = a4.x; As[lk + 1][lr] = a4.y;
        As[lk + 2][lr] = a4.z; As[lk + 3][lr] = a4.w;
        Bs[lk + 0][lr] = b4.x; Bs[lk + 1][lr] = b4.y;
        Bs[lk + 2][lr] = b4.z; Bs[lk + 3][lr] = b4.w;
        __syncthreads();
        #pragma unroll
        for (int k = 0; k < 8; k++) {
            float a[8], bb[8];
            #pragma unroll
            for (int i = 0; i < 8; i++) a[i]  = As[k][ty * 8 + i];
            #pragma unroll
            for (int j = 0; j < 8; j++) bb[j] = Bs[k][tx * 8 + j];
            #pragma unroll
            for (int i = 0; i < 8; i++)
                #pragma unroll
                for (int j = 0; j < 8; j++)
                    acc[i][j] += a[i] * bb[j];
        }
        __syncthreads();
    }

    float bv[8];
    #pragma unroll
    for (int j = 0; j < 8; j++) bv[j] = bias[col0 + tx * 8 + j];

    #pragma unroll
    for (int i = 0; i < 8; i++) {
        int r = row0 + ty * 8 + i;
        size_t off = (size_t)r * Dout + col0 + tx * 8;
        float o[8];
        #pragma unroll
        for (int j = 0; j < 8; j++) {
            float v = acc[i][j] + bv[j];
            if (EPI == 1)
                v = 0.5f * v * (1.0f + erff(v * 0.70710678118654752f));
            o[j] = v;
        }
        if (EPI == 2) {
            float4 r0 = *(const float4*)(res + off);
            float4 r1 = *(const float4*)(res + off + 4);
            o[0] += r0.x; o[1] += r0.y; o[2] += r0.z; o[3] += r0.w;
            o[4] += r1.x; o[5] += r1.y; o[6] += r1.z; o[7] += r1.w;
        }
        *(float4*)(C + off)     = make_float4(o[0], o[1], o[2], o[3]);
        *(float4*)(C + off + 4) = make_float4(o[4], o[5], o[6], o[7]);
    }
}

// ---------------------------------------------------------------------------
// Fused attention per (bm, head): scores -> softmax -> A@V
// grid = 2048*8, 256 threads, dynamic smem
// ---------------------------------------------------------------------------
#define ATTN_SMEM_FLOATS (81 * 65 * 3 + 81 * 82)
__global__ void attn_kernel(const float* __restrict__ q,
                            const float* __restrict__ k,
                            const float* __restrict__ v,
                            float* __restrict__ o)
{
    extern __shared__ float sm[];
    float* qs = sm;                  // [81][65]
    float* ks = qs + 81 * 65;
    float* vs = ks + 81 * 65;
    float* ss = vs + 81 * 65;        // [81][82]
    int bmh = blockIdx.x;
    int bm = bmh >> 3, hh = bmh & 7;
    int tid = threadIdx.x;
    size_t base = (size_t)bm * NTOK * DM + hh * EH;

    for (int i = tid; i < NTOK * EH; i += 256) {
        int n = i >> 6, e = i & 63;
        size_t g = base + (size_t)n * DM + e;
        qs[n * 65 + e] = q[g];
        ks[n * 65 + e] = k[g];
        vs[n * 65 + e] = v[g];
    }
    __syncthreads();

    for (int i = tid; i < NTOK * NTOK; i += 256) {
        int l = i / NTOK, s2 = i - l * NTOK;
        float acc = 0.f;
        const float* qr = qs + l * 65;
        const float* kr = ks + s2 * 65;
        #pragma unroll 16
        for (int e = 0; e < EH; e++) acc += qr[e] * kr[e];
        ss[l * 82 + s2] = acc * 0.125f;   // 1/sqrt(64)
    }
    __syncthreads();

    if (tid < NTOK) {
        float* row = ss + tid * 82;
        float mx = -1e30f;
        for (int s2 = 0; s2 < NTOK; s2++) mx = fmaxf(mx, row[s2]);
        float sum = 0.f;
        for (int s2 = 0; s2 < NTOK; s2++) {
            float t = expf(row[s2] - mx);
            row[s2] = t; sum += t;
        }
        float inv = 1.0f / sum;
        for (int s2 = 0; s2 < NTOK; s2++) row[s2] *= inv;
    }
    __syncthreads();

    for (int i = tid; i < NTOK * EH; i += 256) {
        int l = i >> 6, e = i & 63;
        float acc = 0.f;
        const float* ar = ss + l * 82;
        #pragma unroll 9
        for (int s2 = 0; s2 < NTOK; s2++) acc += ar[s2] * vs[s2 * 65 + e];
        o[base + (size_t)l * DM + e] = acc;
    }
}

// ---------------------------------------------------------------------------
// BatchNorm (train-mode, population stats over all 165888 rows per channel)
// Deterministic two-stage reduction (no float atomics).
// ---------------------------------------------------------------------------
__global__ void bn_reduce1_kernel(const float* __restrict__ y)
{
    int c = threadIdx.x;                       // 512 threads = 512 channels
    const float* p = y + (size_t)blockIdx.x * 324 * DM + c;
    float s = 0.f, q = 0.f;
    #pragma unroll 4
    for (int i = 0; i < 324; i++) {
        float vv = p[(size_t)i * DM];
        s += vv; q += vv * vv;
    }
    g_psum[blockIdx.x * 512 + c] = s;
    g_psq [blockIdx.x * 512 + c] = q;
}

__global__ void bn_reduce2_kernel(const float* __restrict__ gamma,
                                  const float* __restrict__ beta)
{
    int c = blockIdx.x * 256 + threadIdx.x;
    float s = 0.f, q = 0.f;
    for (int j = 0; j < 512; j++) {
        s += g_psum[j * 512 + c];
        q += g_psq [j * 512 + c];
    }
    const float invn = 1.0f / (float)RT;
    float mu  = s * invn;
    float var = q * invn - mu * mu;
    float rinv = rsqrtf(var + 1e-5f);
    float sc = rinv * gamma[c];
    g_scale[c] = sc;
    g_shift[c] = beta[c] - mu * sc;
}

__global__ void bn_norm_kernel(const float* __restrict__ y, float* __restrict__ out)
{
    const int total = RT * DM / 4;
    for (int i = blockIdx.x * blockDim.x + threadIdx.x; i < total;
         i += gridDim.x * blockDim.x) {
        float4 vv = ((const float4*)y)[i];
        int c = (i & 127) * 4;
        float4 oo;
        oo.x = vv.x * g_scale[c + 0] + g_shift[c + 0];
        oo.y = vv.y * g_scale[c + 1] + g_shift[c + 1];
        oo.z = vv.z * g_scale[c + 2] + g_shift[c + 2];
        oo.w = vv.w * g_scale[c + 3] + g_shift[c + 3];
        ((float4*)out)[i] = oo;
    }
}

// ---------------------------------------------------------------------------
// Orchestration
// ---------------------------------------------------------------------------
extern "C" void kernel_launch(void* const* d_in, const int* in_sizes, int n_in,
                              void* d_out, int out_size)
{
    const float* x_enc = (const float*)d_in[0];
    const float* tok_w = (const float*)d_in[1];
    const float* wq  = (const float*)d_in[2];
    const float* bq  = (const float*)d_in[3];
    const float* wk  = (const float*)d_in[4];
    const float* bk  = (const float*)d_in[5];
    const float* wv  = (const float*)d_in[6];
    const float* bv  = (const float*)d_in[7];
    const float* wo  = (const float*)d_in[8];
    const float* bo  = (const float*)d_in[9];
    const float* c1w = (const float*)d_in[10];
    const float* c1b = (const float*)d_in[11];
    const float* c2w = (const float*)d_in[12];
    const float* c2b = (const float*)d_in[13];
    const float* g1  = (const float*)d_in[14];
    const float* be1 = (const float*)d_in[15];
    const float* g2  = (const float*)d_in[16];
    const float* be2 = (const float*)d_in[17];
    float* out = (float*)d_out;

    float *p_h, *p_q, *p_k, *p_v, *p_att, *p_y, *p_t;
    cudaGetSymbolAddress((void**)&p_h,   g_h);
    cudaGetSymbolAddress((void**)&p_q,   g_q);
    cudaGetSymbolAddress((void**)&p_k,   g_k);
    cudaGetSymbolAddress((void**)&p_v,   g_v);
    cudaGetSymbolAddress((void**)&p_att, g_att);
    cudaGetSymbolAddress((void**)&p_y,   g_y);
    cudaGetSymbolAddress((void**)&p_t,   g_t);

    const int EMB_SMEM  = EMB_SMEM_FLOATS  * 4;
    const int ATTN_SMEM = ATTN_SMEM_FLOATS * 4;
    cudaFuncSetAttribute(embed_kernel,
        cudaFuncAttributeMaxDynamicSharedMemorySize, EMB_SMEM);
    cudaFuncSetAttribute(attn_kernel,
        cudaFuncAttributeMaxDynamicSharedMemorySize, ATTN_SMEM);

    embed_kernel<<<2048, 256, EMB_SMEM>>>(x_enc, tok_w, p_h);

    for (int l = 0; l < NL; l++) {
        const int WOFF = l * DM * DM;        // 262144
        const int FOFF = l * DFF * DM;       // 524288

        sgemm_kernel<0><<<dim3(4, RTILES), 256>>>(p_h, wq + WOFF, bq + l * DM,
                                                  nullptr, p_q, DM);
        sgemm_kernel<0><<<dim3(4, RTILES), 256>>>(p_h, wk + WOFF, bk + l * DM,
                                                  nullptr, p_k, DM);
        sgemm_kernel<0><<<dim3(4, RTILES), 256>>>(p_h, wv + WOFF, bv + l * DM,
                                                  nullptr, p_v, DM);

        attn_kernel<<<2048 * NH, 256, ATTN_SMEM>>>(p_q, p_k, p_v, p_att);

        sgemm_kernel<2><<<dim3(4, RTILES), 256>>>(p_att, wo + WOFF, bo + l * DM,
                                                  p_h, p_y, DM);
        bn_reduce1_kernel<<<512, 512>>>(p_y);
        bn_reduce2_kernel<<<2, 256>>>(g1 + l * DM, be1 + l * DM);
        bn_norm_kernel<<<4096, 256>>>(p_y, p_h);

        sgemm_kernel<1><<<dim3(8, RTILES), 256>>>(p_h, c1w + FOFF, c1b + l * DFF,
                                                  nullptr, p_t, DM);
        sgemm_kernel<2><<<dim3(4, RTILES), 256>>>(p_t, c2w + FOFF, c2b + l * DM,
                                                  p_h, p_y, DFF);
        bn_reduce1_kernel<<<512, 512>>>(p_y);
        bn_reduce2_kernel<<<2, 256>>>(g2 + l * DM, be2 + l * DM);
        bn_norm_kernel<<<4096, 256>>>(p_y, (l == NL - 1) ? out : p_h);
    }
}

// round 4
// speedup vs baseline: 2.1608x; 2.1608x over previous
#include <cuda_runtime.h>
#include <math.h>
#include <stdint.h>

// ---------------------------------------------------------------------------
// Problem constants
// ---------------------------------------------------------------------------
#define BB     32
#define L_IN   336
#define MM     64
#define PP     16
#define STRIDE 4
#define NTOK   81                    // (336-16)/4 + 1
#define DM     512
#define NH     8
#define EH     64
#define DFF    1024
#define NL     3
#define RT     (2048 * 81)           // 165888 tokens total (B*M*N)
#define RTILES (RT / 128)            // 1296

// ---------------------------------------------------------------------------
// Scratch (device globals: no cudaMalloc allowed)
// ---------------------------------------------------------------------------
__device__ float g_h  [RT * DM];
__device__ float g_q  [RT * DM];
__device__ float g_k  [RT * DM];
__device__ float g_v  [RT * DM];
__device__ float g_att[RT * DM];
__device__ float g_y  [RT * DM];
__device__ float g_t  [RT * DFF];
__device__ float g_psum[512 * 512];
__device__ float g_psq [512 * 512];
__device__ float g_scale[512];
__device__ float g_shift[512];

// ---------------------------------------------------------------------------
// tf32 helpers (family-compatible PTX: mma.sync is sm_80+, compiles at compute_103)
// ---------------------------------------------------------------------------
__device__ __forceinline__ float tf32r(float x) {
    float y;
    asm("cvt.rna.tf32.f32 %0, %1;" : "=f"(y) : "f"(x));
    return y;
}

__device__ __forceinline__ void mma_tf32(float* c, const uint32_t* a, const uint32_t* b) {
    asm volatile(
        "mma.sync.aligned.m16n8k8.row.col.f32.tf32.tf32.f32 "
        "{%0,%1,%2,%3}, {%4,%5,%6,%7}, {%8,%9}, {%0,%1,%2,%3};"
        : "+f"(c[0]), "+f"(c[1]), "+f"(c[2]), "+f"(c[3])
        : "r"(a[0]), "r"(a[1]), "r"(a[2]), "r"(a[3]), "r"(b[0]), "r"(b[1]));
}

// ---------------------------------------------------------------------------
// TF32 tensor-core GEMM: C[r,o] = sum_k A[r,k]*W[o,k] (+bias; EPI 0/1/2)
// CTA tile 128x128, BK=16, 256 threads = 8 warps (2x4), warp tile 64x32.
// Double-buffered smem, LDG->reg prefetch, one barrier per K-iter.
// grid = (Dout/128, RT/128). EPI: 0=bias, 1=bias+gelu, 2=bias+residual
// ---------------------------------------------------------------------------
#define APAD 20

template <int EPI>
__global__ __launch_bounds__(256)
void mma_gemm(const float* __restrict__ A, const float* __restrict__ W,
              const float* __restrict__ bias, const float* __restrict__ res,
              float* __restrict__ C, int K)
{
    __shared__ float As[2][128][APAD];   // 2 x 10240 B
    __shared__ float Bs[2][128][APAD];   // 2 x 10240 B  (total 40 KB)

    int tid  = threadIdx.x;
    int wid  = tid >> 5, lane = tid & 31;
    int wm   = (wid >> 2) * 64;          // warp row offset in tile
    int wn   = (wid & 3) * 32;           // warp col offset in tile
    int row0 = blockIdx.y * 128, col0 = blockIdx.x * 128;
    int Dout = gridDim.x * 128;
    int qg   = lane >> 2;                // quad group 0..7
    int qt   = lane & 3;                 // thread-in-quad 0..3

    // gmem tile mapping: 2 float4 per thread per operand
    int r_ld[2], kq_ld[2];
    #pragma unroll
    for (int i = 0; i < 2; i++) {
        int lin = tid + 256 * i;
        r_ld[i]  = lin >> 2;             // 0..127
        kq_ld[i] = lin & 3;              // float4 index within BK=16
    }

    float4 pa[2], pb[2];
    #pragma unroll
    for (int i = 0; i < 2; i++) {
        pa[i] = *(const float4*)(A + (size_t)(row0 + r_ld[i]) * K + kq_ld[i] * 4);
        pb[i] = *(const float4*)(W + (size_t)(col0 + r_ld[i]) * K + kq_ld[i] * 4);
    }
    #pragma unroll
    for (int i = 0; i < 2; i++) {
        float4 va = pa[i], vb = pb[i];
        va.x = tf32r(va.x); va.y = tf32r(va.y); va.z = tf32r(va.z); va.w = tf32r(va.w);
        vb.x = tf32r(vb.x); vb.y = tf32r(vb.y); vb.z = tf32r(vb.z); vb.w = tf32r(vb.w);
        *(float4*)&As[0][r_ld[i]][kq_ld[i] * 4] = va;
        *(float4*)&Bs[0][r_ld[i]][kq_ld[i] * 4] = vb;
    }
    __syncthreads();

    float acc[4][4][4];
    #pragma unroll
    for (int mt = 0; mt < 4; mt++)
        #pragma unroll
        for (int nt = 0; nt < 4; nt++)
            #pragma unroll
            for (int j = 0; j < 4; j++) acc[mt][nt][j] = 0.f;

    int NKB = K / 16;
    for (int kb = 0; kb < NKB; kb++) {
        int cur = kb & 1, nxt = cur ^ 1;
        if (kb + 1 < NKB) {
            int kOff = (kb + 1) * 16;
            #pragma unroll
            for (int i = 0; i < 2; i++) {
                pa[i] = *(const float4*)(A + (size_t)(row0 + r_ld[i]) * K + kOff + kq_ld[i] * 4);
                pb[i] = *(const float4*)(W + (size_t)(col0 + r_ld[i]) * K + kOff + kq_ld[i] * 4);
            }
        }

        #pragma unroll
        for (int ks = 0; ks < 2; ks++) {
            int k0 = ks * 8;
            uint32_t af[4][4], bf[4][2];
            #pragma unroll
            for (int mt = 0; mt < 4; mt++) {
                int m = wm + mt * 16 + qg;
                af[mt][0] = __float_as_uint(As[cur][m    ][k0 + qt    ]);
                af[mt][1] = __float_as_uint(As[cur][m + 8][k0 + qt    ]);
                af[mt][2] = __float_as_uint(As[cur][m    ][k0 + qt + 4]);
                af[mt][3] = __float_as_uint(As[cur][m + 8][k0 + qt + 4]);
            }
            #pragma unroll
            for (int nt = 0; nt < 4; nt++) {
                int n = wn + nt * 8 + qg;
                bf[nt][0] = __float_as_uint(Bs[cur][n][k0 + qt    ]);
                bf[nt][1] = __float_as_uint(Bs[cur][n][k0 + qt + 4]);
            }
            #pragma unroll
            for (int mt = 0; mt < 4; mt++)
                #pragma unroll
                for (int nt = 0; nt < 4; nt++)
                    mma_tf32(acc[mt][nt], af[mt], bf[nt]);
        }

        if (kb + 1 < NKB) {
            #pragma unroll
            for (int i = 0; i < 2; i++) {
                float4 va = pa[i], vb = pb[i];
                va.x = tf32r(va.x); va.y = tf32r(va.y); va.z = tf32r(va.z); va.w = tf32r(va.w);
                vb.x = tf32r(vb.x); vb.y = tf32r(vb.y); vb.z = tf32r(vb.z); vb.w = tf32r(vb.w);
                *(float4*)&As[nxt][r_ld[i]][kq_ld[i] * 4] = va;
                *(float4*)&Bs[nxt][r_ld[i]][kq_ld[i] * 4] = vb;
            }
        }
        __syncthreads();
    }

    // epilogue
    #pragma unroll
    for (int mt = 0; mt < 4; mt++) {
        #pragma unroll
        for (int nt = 0; nt < 4; nt++) {
            int c  = col0 + wn + nt * 8 + 2 * qt;
            int r0 = row0 + wm + mt * 16 + qg;
            float b0 = bias[c], b1 = bias[c + 1];
            #pragma unroll
            for (int half = 0; half < 2; half++) {
                int r = r0 + half * 8;
                float vx = acc[mt][nt][half * 2 + 0] + b0;
                float vy = acc[mt][nt][half * 2 + 1] + b1;
                if (EPI == 1) {
                    vx = 0.5f * vx * (1.0f + erff(vx * 0.70710678118654752f));
                    vy = 0.5f * vy * (1.0f + erff(vy * 0.70710678118654752f));
                }
                size_t off = (size_t)r * Dout + c;
                if (EPI == 2) {
                    float2 rv = *(const float2*)(res + off);
                    vx += rv.x; vy += rv.y;
                }
                *(float2*)(C + off) = make_float2(vx, vy);
            }
        }
    }
}

// ---------------------------------------------------------------------------
// Token embedding (unchanged from R2)
// ---------------------------------------------------------------------------
#define EMB_SMEM_FLOATS (512 * 49 + 336)
__global__ void embed_kernel(const float* __restrict__ x_enc,
                             const float* __restrict__ tok_w,
                             float* __restrict__ h)
{
    extern __shared__ float sm[];
    float* w_sm = sm;
    float* x_sm = sm + 512 * 49;
    int bm = blockIdx.x;
    int b = bm >> 6, m = bm & 63;
    int tid = threadIdx.x;

    for (int i = tid; i < 512 * 48; i += 256) {
        int d = i / 48, u = i - d * 48;
        w_sm[d * 49 + u] = tok_w[i];
    }
    for (int l = tid; l < 336; l += 256)
        x_sm[l] = x_enc[(b * 336 + l) * 64 + m];
    __syncthreads();

    const float CLOG = -9.210340371976184f / 256.0f;
    int d0 = tid, d1 = tid + 256;
    float fr0 = expf((float)(d0 >> 1) * CLOG);
    float fr1 = expf((float)(d1 >> 1) * CLOG);

    for (int n = 0; n < NTOK; n++) {
        float a0 = 0.f, a1 = 0.f;
        #pragma unroll
        for (int t = 0; t < 3; t++) {
            int pp = n - 1 + t;
            pp = (pp < 0) ? (NTOK - 1) : (pp >= NTOK ? 0 : pp);
            const float* xp = x_sm + pp * 4;
            #pragma unroll
            for (int p = 0; p < 16; p++) {
                float xv = xp[p];
                a0 += xv * w_sm[d0 * 49 + p * 3 + t];
                a1 += xv * w_sm[d1 * 49 + p * 3 + t];
            }
        }
        float ang0 = (float)n * fr0, ang1 = (float)n * fr1;
        float pe0 = (d0 & 1) ? cosf(ang0) : sinf(ang0);
        float pe1 = (d1 & 1) ? cosf(ang1) : sinf(ang1);
        size_t base = ((size_t)bm * NTOK + n) * DM;
        h[base + d0] = a0 + pe0;
        h[base + d1] = a1 + pe1;
    }
}

// ---------------------------------------------------------------------------
// Fused attention per (bm, head) (unchanged from R2)
// ---------------------------------------------------------------------------
#define ATTN_SMEM_FLOATS (81 * 65 * 3 + 81 * 82)
__global__ void attn_kernel(const float* __restrict__ q,
                            const float* __restrict__ k,
                            const float* __restrict__ v,
                            float* __restrict__ o)
{
    extern __shared__ float sm[];
    float* qs = sm;
    float* ks = qs + 81 * 65;
    float* vs = ks + 81 * 65;
    float* ss = vs + 81 * 65;
    int bmh = blockIdx.x;
    int bm = bmh >> 3, hh = bmh & 7;
    int tid = threadIdx.x;
    size_t base = (size_t)bm * NTOK * DM + hh * EH;

    for (int i = tid; i < NTOK * EH; i += 256) {
        int n = i >> 6, e = i & 63;
        size_t g = base + (size_t)n * DM + e;
        qs[n * 65 + e] = q[g];
        ks[n * 65 + e] = k[g];
        vs[n * 65 + e] = v[g];
    }
    __syncthreads();

    for (int i = tid; i < NTOK * NTOK; i += 256) {
        int l = i / NTOK, s2 = i - l * NTOK;
        float acc = 0.f;
        const float* qr = qs + l * 65;
        const float* kr = ks + s2 * 65;
        #pragma unroll 16
        for (int e = 0; e < EH; e++) acc += qr[e] * kr[e];
        ss[l * 82 + s2] = acc * 0.125f;
    }
    __syncthreads();

    if (tid < NTOK) {
        float* row = ss + tid * 82;
        float mx = -1e30f;
        for (int s2 = 0; s2 < NTOK; s2++) mx = fmaxf(mx, row[s2]);
        float sum = 0.f;
        for (int s2 = 0; s2 < NTOK; s2++) {
            float t = expf(row[s2] - mx);
            row[s2] = t; sum += t;
        }
        float inv = 1.0f / sum;
        for (int s2 = 0; s2 < NTOK; s2++) row[s2] *= inv;
    }
    __syncthreads();

    for (int i = tid; i < NTOK * EH; i += 256) {
        int l = i >> 6, e = i & 63;
        float acc = 0.f;
        const float* ar = ss + l * 82;
        #pragma unroll 9
        for (int s2 = 0; s2 < NTOK; s2++) acc += ar[s2] * vs[s2 * 65 + e];
        o[base + (size_t)l * DM + e] = acc;
    }
}

// ---------------------------------------------------------------------------
// BatchNorm (unchanged from R2)
// ---------------------------------------------------------------------------
__global__ void bn_reduce1_kernel(const float* __restrict__ y)
{
    int c = threadIdx.x;
    const float* p = y + (size_t)blockIdx.x * 324 * DM + c;
    float s = 0.f, q = 0.f;
    #pragma unroll 4
    for (int i = 0; i < 324; i++) {
        float vv = p[(size_t)i * DM];
        s += vv; q += vv * vv;
    }
    g_psum[blockIdx.x * 512 + c] = s;
    g_psq [blockIdx.x * 512 + c] = q;
}

__global__ void bn_reduce2_kernel(const float* __restrict__ gamma,
                                  const float* __restrict__ beta)
{
    int c = blockIdx.x * 256 + threadIdx.x;
    float s = 0.f, q = 0.f;
    for (int j = 0; j < 512; j++) {
        s += g_psum[j * 512 + c];
        q += g_psq [j * 512 + c];
    }
    const float invn = 1.0f / (float)RT;
    float mu  = s * invn;
    float var = q * invn - mu * mu;
    float rinv = rsqrtf(var + 1e-5f);
    float sc = rinv * gamma[c];
    g_scale[c] = sc;
    g_shift[c] = beta[c] - mu * sc;
}

__global__ void bn_norm_kernel(const float* __restrict__ y, float* __restrict__ out)
{
    const int total = RT * DM / 4;
    for (int i = blockIdx.x * blockDim.x + threadIdx.x; i < total;
         i += gridDim.x * blockDim.x) {
        float4 vv = ((const float4*)y)[i];
        int c = (i & 127) * 4;
        float4 oo;
        oo.x = vv.x * g_scale[c + 0] + g_shift[c + 0];
        oo.y = vv.y * g_scale[c + 1] + g_shift[c + 1];
        oo.z = vv.z * g_scale[c + 2] + g_shift[c + 2];
        oo.w = vv.w * g_scale[c + 3] + g_shift[c + 3];
        ((float4*)out)[i] = oo;
    }
}

// ---------------------------------------------------------------------------
// Orchestration
// ---------------------------------------------------------------------------
extern "C" void kernel_launch(void* const* d_in, const int* in_sizes, int n_in,
                              void* d_out, int out_size)
{
    const float* x_enc = (const float*)d_in[0];
    const float* tok_w = (const float*)d_in[1];
    const float* wq  = (const float*)d_in[2];
    const float* bq  = (const float*)d_in[3];
    const float* wk  = (const float*)d_in[4];
    const float* bk  = (const float*)d_in[5];
    const float* wv  = (const float*)d_in[6];
    const float* bv  = (const float*)d_in[7];
    const float* wo  = (const float*)d_in[8];
    const float* bo  = (const float*)d_in[9];
    const float* c1w = (const float*)d_in[10];
    const float* c1b = (const float*)d_in[11];
    const float* c2w = (const float*)d_in[12];
    const float* c2b = (const float*)d_in[13];
    const float* g1  = (const float*)d_in[14];
    const float* be1 = (const float*)d_in[15];
    const float* g2  = (const float*)d_in[16];
    const float* be2 = (const float*)d_in[17];
    float* out = (float*)d_out;

    float *p_h, *p_q, *p_k, *p_v, *p_att, *p_y, *p_t;
    cudaGetSymbolAddress((void**)&p_h,   g_h);
    cudaGetSymbolAddress((void**)&p_q,   g_q);
    cudaGetSymbolAddress((void**)&p_k,   g_k);
    cudaGetSymbolAddress((void**)&p_v,   g_v);
    cudaGetSymbolAddress((void**)&p_att, g_att);
    cudaGetSymbolAddress((void**)&p_y,   g_y);
    cudaGetSymbolAddress((void**)&p_t,   g_t);

    const int EMB_SMEM  = EMB_SMEM_FLOATS  * 4;
    const int ATTN_SMEM = ATTN_SMEM_FLOATS * 4;
    cudaFuncSetAttribute(embed_kernel,
        cudaFuncAttributeMaxDynamicSharedMemorySize, EMB_SMEM);
    cudaFuncSetAttribute(attn_kernel,
        cudaFuncAttributeMaxDynamicSharedMemorySize, ATTN_SMEM);

    embed_kernel<<<2048, 256, EMB_SMEM>>>(x_enc, tok_w, p_h);

    for (int l = 0; l < NL; l++) {
        const int WOFF = l * DM * DM;
        const int FOFF = l * DFF * DM;

        mma_gemm<0><<<dim3(4, RTILES), 256>>>(p_h, wq + WOFF, bq + l * DM,
                                              nullptr, p_q, DM);
        mma_gemm<0><<<dim3(4, RTILES), 256>>>(p_h, wk + WOFF, bk + l * DM,
                                              nullptr, p_k, DM);
        mma_gemm<0><<<dim3(4, RTILES), 256>>>(p_h, wv + WOFF, bv + l * DM,
                                              nullptr, p_v, DM);

        attn_kernel<<<2048 * NH, 256, ATTN_SMEM>>>(p_q, p_k, p_v, p_att);

        mma_gemm<2><<<dim3(4, RTILES), 256>>>(p_att, wo + WOFF, bo + l * DM,
                                              p_h, p_y, DM);
        bn_reduce1_kernel<<<512, 512>>>(p_y);
        bn_reduce2_kernel<<<2, 256>>>(g1 + l * DM, be1 + l * DM);
        bn_norm_kernel<<<4096, 256>>>(p_y, p_h);

        mma_gemm<1><<<dim3(8, RTILES), 256>>>(p_h, c1w + FOFF, c1b + l * DFF,
                                              nullptr, p_t, DM);
        mma_gemm<2><<<dim3(4, RTILES), 256>>>(p_t, c2w + FOFF, c2b + l * DM,
                                              p_h, p_y, DFF);
        bn_reduce1_kernel<<<512, 512>>>(p_y);
        bn_reduce2_kernel<<<2, 256>>>(g2 + l * DM, be2 + l * DM);
        bn_norm_kernel<<<4096, 256>>>(p_y, (l == NL - 1) ? out : p_h);
    }
}

// round 5
// speedup vs baseline: 2.9996x; 1.3882x over previous
#include <cuda_runtime.h>
#include <math.h>
#include <stdint.h>

// ---------------------------------------------------------------------------
// Problem constants
// ---------------------------------------------------------------------------
#define NTOK   81
#define DM     512
#define NH     8
#define EH     64
#define DFF    1024
#define NL     3
#define RT     (2048 * 81)           // 165888 tokens total (B*M*N)
#define RTILES (RT / 128)            // 1296

// ---------------------------------------------------------------------------
// Scratch (device globals: no cudaMalloc allowed)
// ---------------------------------------------------------------------------
__device__ float g_h  [RT * DM];     // embed output / y2 (post-FFN pre-norm)
__device__ float g_q  [RT * DM];
__device__ float g_k  [RT * DM];
__device__ float g_v  [RT * DM];
__device__ float g_att[RT * DM];
__device__ float g_y  [RT * DM];     // y1 (post-attn pre-norm)
__device__ float g_t  [RT * DFF];
__device__ float g_psum[512 * 512];
__device__ float g_psq [512 * 512];
__device__ float g_bnscale[2 * 512]; // slot0=BN1, slot1=BN2
__device__ float g_bnshift[2 * 512];

// ---------------------------------------------------------------------------
// tf32 / ldmatrix helpers
// ---------------------------------------------------------------------------
__device__ __forceinline__ float tf32r(float x) {
    float y;
    asm("cvt.rna.tf32.f32 %0, %1;" : "=f"(y) : "f"(x));
    return y;
}

__device__ __forceinline__ void mma_tf32(float* c, const uint32_t* a, const uint32_t* b) {
    asm volatile(
        "mma.sync.aligned.m16n8k8.row.col.f32.tf32.tf32.f32 "
        "{%0,%1,%2,%3}, {%4,%5,%6,%7}, {%8,%9}, {%0,%1,%2,%3};"
        : "+f"(c[0]), "+f"(c[1]), "+f"(c[2]), "+f"(c[3])
        : "r"(a[0]), "r"(a[1]), "r"(a[2]), "r"(a[3]), "r"(b[0]), "r"(b[1]));
}

__device__ __forceinline__ void ldsm_x4(uint32_t* r, uint32_t addr) {
    asm volatile("ldmatrix.sync.aligned.m8n8.x4.shared.b16 {%0,%1,%2,%3}, [%4];"
        : "=r"(r[0]), "=r"(r[1]), "=r"(r[2]), "=r"(r[3]) : "r"(addr));
}

// ---------------------------------------------------------------------------
// TF32 tensor-core GEMM: C[r,o] = sum_k A[r,k]*W[o,k] (+bias)
// CTA tile 128x128, BK=16, 8 warps (2x4), warp tile 64x32, ldmatrix fragments.
// EPI: 0=bias, 1=bias+gelu, 2=bias+residual
// AFF: 0=none, 1=affine on A load (A := scl[k]*A+shf[k]),
//      2=affine on residual (res := scl[c]*res+shf[c])
// ---------------------------------------------------------------------------
#define APAD 20

template <int EPI, int AFF>
__global__ __launch_bounds__(256)
void mma_gemm(const float* __restrict__ A, const float* __restrict__ W,
              const float* __restrict__ bias, const float* __restrict__ res,
              const float* __restrict__ scl, const float* __restrict__ shf,
              float* __restrict__ C, int K)
{
    __shared__ float As[2][128][APAD];
    __shared__ float Bs[2][128][APAD];

    int tid  = threadIdx.x;
    int wid  = tid >> 5, lane = tid & 31;
    int wm   = (wid >> 2) * 64;
    int wn   = (wid & 3) * 32;
    int row0 = blockIdx.y * 128, col0 = blockIdx.x * 128;
    int Dout = gridDim.x * 128;
    int qg   = lane >> 2, qt = lane & 3;
    int lg   = lane >> 3, lr = lane & 7;   // ldmatrix grouping

    // ldmatrix base addresses (per-thread invariant)
    uint32_t asu = (uint32_t)__cvta_generic_to_shared(&As[0][0][0]);
    uint32_t bsu = (uint32_t)__cvta_generic_to_shared(&Bs[0][0][0]);
    uint32_t baseA[4], baseB[2];
    #pragma unroll
    for (int mt = 0; mt < 4; mt++)
        baseA[mt] = asu + (((wm + mt * 16 + (lg & 1) * 8 + lr) * APAD) + (lg >> 1) * 4) * 4;
    #pragma unroll
    for (int p = 0; p < 2; p++)
        baseB[p]  = bsu + (((wn + (2 * p + (lg >> 1)) * 8 + lr) * APAD) + (lg & 1) * 4) * 4;
    const uint32_t BUF = 128 * APAD * 4;

    // gmem tile mapping: 2 float4 per thread per operand
    int r_ld[2], kq_ld[2];
    #pragma unroll
    for (int i = 0; i < 2; i++) {
        int lin = tid + 256 * i;
        r_ld[i]  = lin >> 2;
        kq_ld[i] = lin & 3;
    }

    float4 pa[2], pb[2];
    #pragma unroll
    for (int i = 0; i < 2; i++) {
        pa[i] = *(const float4*)(A + (size_t)(row0 + r_ld[i]) * K + kq_ld[i] * 4);
        pb[i] = *(const float4*)(W + (size_t)(col0 + r_ld[i]) * K + kq_ld[i] * 4);
    }
    #pragma unroll
    for (int i = 0; i < 2; i++) {
        float4 va = pa[i], vb = pb[i];
        if (AFF == 1) {
            float4 s4 = *(const float4*)(scl + kq_ld[i] * 4);
            float4 h4 = *(const float4*)(shf + kq_ld[i] * 4);
            va.x = s4.x * va.x + h4.x; va.y = s4.y * va.y + h4.y;
            va.z = s4.z * va.z + h4.z; va.w = s4.w * va.w + h4.w;
        }
        va.x = tf32r(va.x); va.y = tf32r(va.y); va.z = tf32r(va.z); va.w = tf32r(va.w);
        vb.x = tf32r(vb.x); vb.y = tf32r(vb.y); vb.z = tf32r(vb.z); vb.w = tf32r(vb.w);
        *(float4*)&As[0][r_ld[i]][kq_ld[i] * 4] = va;
        *(float4*)&Bs[0][r_ld[i]][kq_ld[i] * 4] = vb;
    }
    __syncthreads();

    float acc[4][4][4];
    #pragma unroll
    for (int mt = 0; mt < 4; mt++)
        #pragma unroll
        for (int nt = 0; nt < 4; nt++)
            #pragma unroll
            for (int j = 0; j < 4; j++) acc[mt][nt][j] = 0.f;

    int NKB = K / 16;
    for (int kb = 0; kb < NKB; kb++) {
        int cur = kb & 1, nxt = cur ^ 1;
        if (kb + 1 < NKB) {
            int kOff = (kb + 1) * 16;
            #pragma unroll
            for (int i = 0; i < 2; i++) {
                pa[i] = *(const float4*)(A + (size_t)(row0 + r_ld[i]) * K + kOff + kq_ld[i] * 4);
                pb[i] = *(const float4*)(W + (size_t)(col0 + r_ld[i]) * K + kOff + kq_ld[i] * 4);
            }
        }

        uint32_t cOff = cur * BUF;
        #pragma unroll
        for (int ks = 0; ks < 2; ks++) {
            uint32_t kOffB = cOff + ks * 32;
            uint32_t af[4][4], bf[4][2];
            #pragma unroll
            for (int mt = 0; mt < 4; mt++)
                ldsm_x4(af[mt], baseA[mt] + kOffB);
            #pragma unroll
            for (int p = 0; p < 2; p++) {
                uint32_t t[4];
                ldsm_x4(t, baseB[p] + kOffB);
                bf[2 * p][0] = t[0]; bf[2 * p][1] = t[1];
                bf[2 * p + 1][0] = t[2]; bf[2 * p + 1][1] = t[3];
            }
            #pragma unroll
            for (int mt = 0; mt < 4; mt++)
                #pragma unroll
                for (int nt = 0; nt < 4; nt++)
                    mma_tf32(acc[mt][nt], af[mt], bf[nt]);
        }

        if (kb + 1 < NKB) {
            int kOff = (kb + 1) * 16;
            #pragma unroll
            for (int i = 0; i < 2; i++) {
                float4 va = pa[i], vb = pb[i];
                if (AFF == 1) {
                    float4 s4 = *(const float4*)(scl + kOff + kq_ld[i] * 4);
                    float4 h4 = *(const float4*)(shf + kOff + kq_ld[i] * 4);
                    va.x = s4.x * va.x + h4.x; va.y = s4.y * va.y + h4.y;
                    va.z = s4.z * va.z + h4.z; va.w = s4.w * va.w + h4.w;
                }
                va.x = tf32r(va.x); va.y = tf32r(va.y); va.z = tf32r(va.z); va.w = tf32r(va.w);
                vb.x = tf32r(vb.x); vb.y = tf32r(vb.y); vb.z = tf32r(vb.z); vb.w = tf32r(vb.w);
                *(float4*)&As[nxt][r_ld[i]][kq_ld[i] * 4] = va;
                *(float4*)&Bs[nxt][r_ld[i]][kq_ld[i] * 4] = vb;
            }
        }
        __syncthreads();
    }

    // epilogue
    #pragma unroll
    for (int mt = 0; mt < 4; mt++) {
        #pragma unroll
        for (int nt = 0; nt < 4; nt++) {
            int c  = col0 + wn + nt * 8 + 2 * qt;
            int r0 = row0 + wm + mt * 16 + qg;
            float b0 = bias[c], b1 = bias[c + 1];
            float s0 = 1.f, s1 = 1.f, h0 = 0.f, h1 = 0.f;
            if (AFF == 2) {
                s0 = scl[c]; s1 = scl[c + 1];
                h0 = shf[c]; h1 = shf[c + 1];
            }
            #pragma unroll
            for (int half = 0; half < 2; half++) {
                int r = r0 + half * 8;
                float vx = acc[mt][nt][half * 2 + 0] + b0;
                float vy = acc[mt][nt][half * 2 + 1] + b1;
                if (EPI == 1) {
                    vx = 0.5f * vx * (1.0f + erff(vx * 0.70710678118654752f));
                    vy = 0.5f * vy * (1.0f + erff(vy * 0.70710678118654752f));
                }
                size_t off = (size_t)r * Dout + c;
                if (EPI == 2) {
                    float2 rv = *(const float2*)(res + off);
                    if (AFF == 2) { vx += s0 * rv.x + h0; vy += s1 * rv.y + h1; }
                    else          { vx += rv.x;           vy += rv.y; }
                }
                *(float2*)(C + off) = make_float2(vx, vy);
            }
        }
    }
}

// ---------------------------------------------------------------------------
// Token embedding: circular Conv1d(P->D,k=3) + sinusoidal PE
// ---------------------------------------------------------------------------
#define EMB_SMEM_FLOATS (512 * 49 + 336)
__global__ void embed_kernel(const float* __restrict__ x_enc,
                             const float* __restrict__ tok_w,
                             float* __restrict__ h)
{
    extern __shared__ float sm[];
    float* w_sm = sm;
    float* x_sm = sm + 512 * 49;
    int bm = blockIdx.x;
    int b = bm >> 6, m = bm & 63;
    int tid = threadIdx.x;

    for (int i = tid; i < 512 * 48; i += 256) {
        int d = i / 48, u = i - d * 48;
        w_sm[d * 49 + u] = tok_w[i];
    }
    for (int l = tid; l < 336; l += 256)
        x_sm[l] = x_enc[(b * 336 + l) * 64 + m];
    __syncthreads();

    const float CLOG = -9.210340371976184f / 256.0f;
    int d0 = tid, d1 = tid + 256;
    float fr0 = expf((float)(d0 >> 1) * CLOG);
    float fr1 = expf((float)(d1 >> 1) * CLOG);

    for (int n = 0; n < NTOK; n++) {
        float a0 = 0.f, a1 = 0.f;
        #pragma unroll
        for (int t = 0; t < 3; t++) {
            int pp = n - 1 + t;
            pp = (pp < 0) ? (NTOK - 1) : (pp >= NTOK ? 0 : pp);
            const float* xp = x_sm + pp * 4;
            #pragma unroll
            for (int p = 0; p < 16; p++) {
                float xv = xp[p];
                a0 += xv * w_sm[d0 * 49 + p * 3 + t];
                a1 += xv * w_sm[d1 * 49 + p * 3 + t];
            }
        }
        float ang0 = (float)n * fr0, ang1 = (float)n * fr1;
        float pe0 = (d0 & 1) ? cosf(ang0) : sinf(ang0);
        float pe1 = (d1 & 1) ? cosf(ang1) : sinf(ang1);
        size_t base = ((size_t)bm * NTOK + n) * DM;
        h[base + d0] = a0 + pe0;
        h[base + d1] = a1 + pe1;
    }
}

// ---------------------------------------------------------------------------
// Fused attention per (bm, head), register-microtiled (3x3 score tiles,
// 3-row x float4 AV tiles) to cut smem bytes/flop ~3x.
// ---------------------------------------------------------------------------
#define QPAD 17                       // float4s per row (68 floats)
#define SPAD 84
#define ATTN_SMEM_FLOATS (3 * 81 * 68 + 81 * SPAD)
__global__ void attn_kernel(const float* __restrict__ q,
                            const float* __restrict__ k,
                            const float* __restrict__ v,
                            float* __restrict__ o)
{
    extern __shared__ float sm[];
    float4* qs4 = (float4*)sm;                    // [81][17]
    float4* ks4 = qs4 + 81 * QPAD;
    float4* vs4 = ks4 + 81 * QPAD;
    float*  ss  = sm + 3 * 81 * 68;               // [81][84]
    int bmh = blockIdx.x;
    int bm = bmh >> 3, hh = bmh & 7;
    int tid = threadIdx.x;
    size_t base = (size_t)bm * NTOK * DM + hh * EH;

    const float4* gq = (const float4*)(q + base);
    const float4* gk = (const float4*)(k + base);
    const float4* gv = (const float4*)(v + base);
    for (int i = tid; i < NTOK * 16; i += 256) {
        int n = i >> 4, e4 = i & 15;
        int gi = n * 128 + e4;
        qs4[n * QPAD + e4] = gq[gi];
        ks4[n * QPAD + e4] = gk[gi];
        vs4[n * QPAD + e4] = gv[gi];
    }
    __syncthreads();

    // scores: 27x27 grid of 3x3 tiles
    for (int i = tid; i < 729; i += 256) {
        int l0 = (i / 27) * 3, s0 = (i % 27) * 3;
        float acc[3][3] = {};
        #pragma unroll 4
        for (int e4 = 0; e4 < 16; e4++) {
            float4 qv[3], kv[3];
            #pragma unroll
            for (int j = 0; j < 3; j++) {
                qv[j] = qs4[(l0 + j) * QPAD + e4];
                kv[j] = ks4[(s0 + j) * QPAD + e4];
            }
            #pragma unroll
            for (int a = 0; a < 3; a++)
                #pragma unroll
                for (int b2 = 0; b2 < 3; b2++)
                    acc[a][b2] += qv[a].x * kv[b2].x + qv[a].y * kv[b2].y
                                + qv[a].z * kv[b2].z + qv[a].w * kv[b2].w;
        }
        #pragma unroll
        for (int a = 0; a < 3; a++)
            #pragma unroll
            for (int b2 = 0; b2 < 3; b2++)
                ss[(l0 + a) * SPAD + s0 + b2] = acc[a][b2] * 0.125f;
    }
    __syncthreads();

    if (tid < NTOK) {
        float* row = ss + tid * SPAD;
        float mx = -1e30f;
        for (int s2 = 0; s2 < NTOK; s2++) mx = fmaxf(mx, row[s2]);
        float sum = 0.f;
        for (int s2 = 0; s2 < NTOK; s2++) {
            float t = expf(row[s2] - mx);
            row[s2] = t; sum += t;
        }
        float inv = 1.0f / sum;
        for (int s2 = 0; s2 < NTOK; s2++) row[s2] *= inv;
    }
    __syncthreads();

    // A@V: 27 x 16 grid of (3 rows x float4) tiles
    float4* go = (float4*)(o + base);
    for (int i = tid; i < 432; i += 256) {
        int l0 = (i / 16) * 3, e4 = i % 16;
        float4 acc[3] = {};
        for (int s2 = 0; s2 < NTOK; s2++) {
            float4 vv = vs4[s2 * QPAD + e4];
            #pragma unroll
            for (int j = 0; j < 3; j++) {
                float a = ss[(l0 + j) * SPAD + s2];
                acc[j].x += a * vv.x; acc[j].y += a * vv.y;
                acc[j].z += a * vv.z; acc[j].w += a * vv.w;
            }
        }
        #pragma unroll
        for (int j = 0; j < 3; j++)
            go[(l0 + j) * 128 + e4] = acc[j];
    }
}

// ---------------------------------------------------------------------------
// BatchNorm stats (train-mode, per-channel over all 165888 rows)
// ---------------------------------------------------------------------------
__global__ void bn_reduce1_kernel(const float* __restrict__ y)
{
    int c = threadIdx.x;
    const float* p = y + (size_t)blockIdx.x * 324 * DM + c;
    float s = 0.f, q = 0.f;
    #pragma unroll 4
    for (int i = 0; i < 324; i++) {
        float vv = p[(size_t)i * DM];
        s += vv; q += vv * vv;
    }
    g_psum[blockIdx.x * 512 + c] = s;
    g_psq [blockIdx.x * 512 + c] = q;
}

__global__ void bn_reduce2_kernel(const float* __restrict__ gamma,
                                  const float* __restrict__ beta,
                                  float* __restrict__ scl,
                                  float* __restrict__ shf)
{
    int c = blockIdx.x * 256 + threadIdx.x;
    float s = 0.f, q = 0.f;
    for (int j = 0; j < 512; j++) {
        s += g_psum[j * 512 + c];
        q += g_psq [j * 512 + c];
    }
    const float invn = 1.0f / (float)RT;
    float mu  = s * invn;
    float var = q * invn - mu * mu;
    float rinv = rsqrtf(var + 1e-5f);
    float sc = rinv * gamma[c];
    scl[c] = sc;
    shf[c] = beta[c] - mu * sc;
}

__global__ void bn_norm_kernel(const float* __restrict__ y,
                               const float* __restrict__ scl,
                               const float* __restrict__ shf,
                               float* __restrict__ out)
{
    const int total = RT * DM / 4;
    for (int i = blockIdx.x * blockDim.x + threadIdx.x; i < total;
         i += gridDim.x * blockDim.x) {
        float4 vv = ((const float4*)y)[i];
        int c = (i & 127) * 4;
        float4 oo;
        oo.x = vv.x * scl[c + 0] + shf[c + 0];
        oo.y = vv.y * scl[c + 1] + shf[c + 1];
        oo.z = vv.z * scl[c + 2] + shf[c + 2];
        oo.w = vv.w * scl[c + 3] + shf[c + 3];
        ((float4*)out)[i] = oo;
    }
}

// ---------------------------------------------------------------------------
// Orchestration
// ---------------------------------------------------------------------------
extern "C" void kernel_launch(void* const* d_in, const int* in_sizes, int n_in,
                              void* d_out, int out_size)
{
    const float* x_enc = (const float*)d_in[0];
    const float* tok_w = (const float*)d_in[1];
    const float* wq  = (const float*)d_in[2];
    const float* bq  = (const float*)d_in[3];
    const float* wk  = (const float*)d_in[4];
    const float* bk  = (const float*)d_in[5];
    const float* wv  = (const float*)d_in[6];
    const float* bv  = (const float*)d_in[7];
    const float* wo  = (const float*)d_in[8];
    const float* bo  = (const float*)d_in[9];
    const float* c1w = (const float*)d_in[10];
    const float* c1b = (const float*)d_in[11];
    const float* c2w = (const float*)d_in[12];
    const float* c2b = (const float*)d_in[13];
    const float* g1  = (const float*)d_in[14];
    const float* be1 = (const float*)d_in[15];
    const float* g2  = (const float*)d_in[16];
    const float* be2 = (const float*)d_in[17];
    float* out = (float*)d_out;

    float *p_h, *p_q, *p_k, *p_v, *p_att, *p_y, *p_t, *p_scl, *p_shf;
    cudaGetSymbolAddress((void**)&p_h,   g_h);
    cudaGetSymbolAddress((void**)&p_q,   g_q);
    cudaGetSymbolAddress((void**)&p_k,   g_k);
    cudaGetSymbolAddress((void**)&p_v,   g_v);
    cudaGetSymbolAddress((void**)&p_att, g_att);
    cudaGetSymbolAddress((void**)&p_y,   g_y);
    cudaGetSymbolAddress((void**)&p_t,   g_t);
    cudaGetSymbolAddress((void**)&p_scl, g_bnscale);
    cudaGetSymbolAddress((void**)&p_shf, g_bnshift);
    float* scl0 = p_scl;       float* shf0 = p_shf;
    float* scl1 = p_scl + 512; float* shf1 = p_shf + 512;

    const int EMB_SMEM  = EMB_SMEM_FLOATS  * 4;
    const int ATTN_SMEM = ATTN_SMEM_FLOATS * 4;
    cudaFuncSetAttribute(embed_kernel,
        cudaFuncAttributeMaxDynamicSharedMemorySize, EMB_SMEM);
    cudaFuncSetAttribute(attn_kernel,
        cudaFuncAttributeMaxDynamicSharedMemorySize, ATTN_SMEM);

    embed_kernel<<<2048, 256, EMB_SMEM>>>(x_enc, tok_w, p_h);

    for (int l = 0; l < NL; l++) {
        const int WOFF = l * DM * DM;
        const int FOFF = l * DFF * DM;

        // q/k/v: A = p_h (embed out for l=0, raw y2 for l>0 with BN2 affine)
        if (l == 0) {
            mma_gemm<0, 0><<<dim3(4, RTILES), 256>>>(p_h, wq + WOFF, bq + l * DM,
                nullptr, nullptr, nullptr, p_q, DM);
            mma_gemm<0, 0><<<dim3(4, RTILES), 256>>>(p_h, wk + WOFF, bk + l * DM,
                nullptr, nullptr, nullptr, p_k, DM);
            mma_gemm<0, 0><<<dim3(4, RTILES), 256>>>(p_h, wv + WOFF, bv + l * DM,
                nullptr, nullptr, nullptr, p_v, DM);
        } else {
            mma_gemm<0, 1><<<dim3(4, RTILES), 256>>>(p_h, wq + WOFF, bq + l * DM,
                nullptr, scl1, shf1, p_q, DM);
            mma_gemm<0, 1><<<dim3(4, RTILES), 256>>>(p_h, wk + WOFF, bk + l * DM,
                nullptr, scl1, shf1, p_k, DM);
            mma_gemm<0, 1><<<dim3(4, RTILES), 256>>>(p_h, wv + WOFF, bv + l * DM,
                nullptr, scl1, shf1, p_v, DM);
        }

        attn_kernel<<<2048 * NH, 256, ATTN_SMEM>>>(p_q, p_k, p_v, p_att);

        // wo: out y1 = att@wo + bo + norm(h_src)
        if (l == 0)
            mma_gemm<2, 0><<<dim3(4, RTILES), 256>>>(p_att, wo + WOFF, bo + l * DM,
                p_h, nullptr, nullptr, p_y, DM);
        else
            mma_gemm<2, 2><<<dim3(4, RTILES), 256>>>(p_att, wo + WOFF, bo + l * DM,
                p_h, scl1, shf1, p_y, DM);

        bn_reduce1_kernel<<<512, 512>>>(p_y);
        bn_reduce2_kernel<<<2, 256>>>(g1 + l * DM, be1 + l * DM, scl0, shf0);

        // FFN: c1 (A=norm1(y1), gelu), c2 (res=norm1(y1)) -> y2 in p_h
        mma_gemm<1, 1><<<dim3(8, RTILES), 256>>>(p_y, c1w + FOFF, c1b + l * DFF,
            nullptr, scl0, shf0, p_t, DM);
        mma_gemm<2, 2><<<dim3(4, RTILES), 256>>>(p_t, c2w + FOFF, c2b + l * DM,
            p_y, scl0, shf0, p_h, DFF);

        bn_reduce1_kernel<<<512, 512>>>(p_h);
        bn_reduce2_kernel<<<2, 256>>>(g2 + l * DM, be2 + l * DM, scl1, shf1);
    }

    bn_norm_kernel<<<4096, 256>>>(p_h, scl1, shf1, out);
}